// round 1
// baseline (speedup 1.0000x reference)
#include <cuda_runtime.h>
#include <cstdint>

// Shapes (fixed): B=4, T=8, C=256, H=W=64 (HW=4096), DH=128
// CK = C*9 = 2304, DK = DH*9 = 1152
#define HW 4096
#define CK 2304

// ---------------- scratch (device globals; allocation-free) ----------------
__device__ float g_k[4 * 128 * 4096];          // k conv result       (8.4 MB)
__device__ float g_g[4 * 4096 * 2304];         // g = k^T * Wq        (151 MB)
__device__ float g_attn[4 * 4096 * 8];         // softmax weights
__device__ float g_y[4 * 2304 * 4096];         // attn-weighted patches (151 MB)
__device__ float g_pooled[4 * 128 * 4096];     // pooled = Wv * y
__device__ float g_outb[4 * 256 * 4096];       // out conv per batch

// ---------------- generic 128x128x8 fp32 GEMM ----------------
// C[m,n] = sum_k A[m*sAm + k*sAk] * B[k*sBk + n]   (n contiguous in B, C row-major ld=N)
// All of M,N multiples of 128; K multiple of 8. No edge checks needed.
template <bool AMC>  // AMC: A is contiguous along m (load tile coalesced over m)
__global__ void __launch_bounds__(256) sgemm128(
    const float* __restrict__ A, const float* __restrict__ B, float* __restrict__ C,
    int M, int N, int K,
    long sAm, long sAk, long sBk,
    long batchA, long batchB, long batchC,
    const float* __restrict__ bias)
{
    __shared__ __align__(16) float As[8][128];
    __shared__ __align__(16) float Bs[8][128];

    const float* Ab = A + (size_t)blockIdx.z * batchA;
    const float* Bb = B + (size_t)blockIdx.z * batchB;
    float*       Cb = C + (size_t)blockIdx.z * batchC;

    const int bm = blockIdx.y * 128;
    const int bn = blockIdx.x * 128;
    const int tid = threadIdx.x;
    const int tx = tid & 15;       // 0..15 -> 8 cols each
    const int ty = tid >> 4;       // 0..15 -> 8 rows each

    float acc[8][8];
#pragma unroll
    for (int i = 0; i < 8; ++i)
#pragma unroll
        for (int j = 0; j < 8; ++j) acc[i][j] = 0.f;

    for (int k0 = 0; k0 < K; k0 += 8) {
#pragma unroll
        for (int r = 0; r < 4; ++r) {
            int idx = tid + r * 256;
            if (AMC) {
                int k = idx >> 7, m = idx & 127;
                As[k][m] = Ab[(size_t)(bm + m) * sAm + (size_t)(k0 + k) * sAk];
            } else {
                int m = idx >> 3, k = idx & 7;
                As[k][m] = Ab[(size_t)(bm + m) * sAm + (size_t)(k0 + k) * sAk];
            }
            int kb = idx >> 7, n = idx & 127;
            Bs[kb][n] = Bb[(size_t)(k0 + kb) * sBk + bn + n];
        }
        __syncthreads();
#pragma unroll
        for (int kk = 0; kk < 8; ++kk) {
            float4 a0 = *(const float4*)&As[kk][ty * 8];
            float4 a1 = *(const float4*)&As[kk][ty * 8 + 4];
            float4 b0 = *(const float4*)&Bs[kk][tx * 8];
            float4 b1 = *(const float4*)&Bs[kk][tx * 8 + 4];
            float av[8] = {a0.x, a0.y, a0.z, a0.w, a1.x, a1.y, a1.z, a1.w};
            float bv[8] = {b0.x, b0.y, b0.z, b0.w, b1.x, b1.y, b1.z, b1.w};
#pragma unroll
            for (int i = 0; i < 8; ++i)
#pragma unroll
                for (int j = 0; j < 8; ++j) acc[i][j] += av[i] * bv[j];
        }
        __syncthreads();
    }

#pragma unroll
    for (int i = 0; i < 8; ++i) {
        float bvv = bias ? bias[bm + ty * 8 + i] : 0.f;
        float* crow = Cb + (size_t)(bm + ty * 8 + i) * N + bn + tx * 8;
        float4 o0 = make_float4(acc[i][0] + bvv, acc[i][1] + bvv, acc[i][2] + bvv, acc[i][3] + bvv);
        float4 o1 = make_float4(acc[i][4] + bvv, acc[i][5] + bvv, acc[i][6] + bvv, acc[i][7] + bvv);
        *(float4*)(crow)     = o0;
        *(float4*)(crow + 4) = o1;
    }
}

// ---------------- 3x3 conv as implicit GEMM (same 128x128x8 core) ----------------
// W: [M][Cin*9] row-major; X: [Cin][64][64] (per batch, stride bsX); out: [M][4096]
__global__ void __launch_bounds__(256) conv3x3(
    const float* __restrict__ W, const float* __restrict__ X, float* __restrict__ Cout,
    int M, int Cin, long bsX, long bsC, const float* __restrict__ bias)
{
    __shared__ __align__(16) float As[8][128];
    __shared__ __align__(16) float Bs[8][128];

    const int K = Cin * 9;
    const float* Xb = X + (size_t)blockIdx.z * bsX;
    float*       Cb = Cout + (size_t)blockIdx.z * bsC;

    const int bm = blockIdx.y * 128;
    const int bn = blockIdx.x * 128;   // 128 pixels = 2 image rows
    const int tid = threadIdx.x;
    const int tx = tid & 15, ty = tid >> 4;

    float acc[8][8];
#pragma unroll
    for (int i = 0; i < 8; ++i)
#pragma unroll
        for (int j = 0; j < 8; ++j) acc[i][j] = 0.f;

    for (int k0 = 0; k0 < K; k0 += 8) {
#pragma unroll
        for (int r = 0; r < 4; ++r) {
            int idx = tid + r * 256;
            {   // A tile: weights row-major
                int m = idx >> 3, k = idx & 7;
                As[k][m] = W[(size_t)(bm + m) * K + k0 + k];
            }
            {   // B tile: implicit im2col
                int kb = k0 + (idx >> 7);
                int n  = idx & 127;
                int c  = kb / 9;
                int j  = kb - c * 9;
                int p  = bn + n;
                int h  = p >> 6, w = p & 63;
                int hi = h + j / 3 - 1;
                int wi = w + (j - (j / 3) * 3) - 1;
                float v = 0.f;
                if ((unsigned)hi < 64u && (unsigned)wi < 64u)
                    v = Xb[(size_t)c * HW + hi * 64 + wi];
                Bs[idx >> 7][n] = v;
            }
        }
        __syncthreads();
#pragma unroll
        for (int kk = 0; kk < 8; ++kk) {
            float4 a0 = *(const float4*)&As[kk][ty * 8];
            float4 a1 = *(const float4*)&As[kk][ty * 8 + 4];
            float4 b0 = *(const float4*)&Bs[kk][tx * 8];
            float4 b1 = *(const float4*)&Bs[kk][tx * 8 + 4];
            float av[8] = {a0.x, a0.y, a0.z, a0.w, a1.x, a1.y, a1.z, a1.w};
            float bv[8] = {b0.x, b0.y, b0.z, b0.w, b1.x, b1.y, b1.z, b1.w};
#pragma unroll
            for (int i = 0; i < 8; ++i)
#pragma unroll
                for (int j = 0; j < 8; ++j) acc[i][j] += av[i] * bv[j];
        }
        __syncthreads();
    }

#pragma unroll
    for (int i = 0; i < 8; ++i) {
        float bvv = bias ? bias[bm + ty * 8 + i] : 0.f;
        float* crow = Cb + (size_t)(bm + ty * 8 + i) * HW + bn + tx * 8;
        float4 o0 = make_float4(acc[i][0] + bvv, acc[i][1] + bvv, acc[i][2] + bvv, acc[i][3] + bvv);
        float4 o1 = make_float4(acc[i][4] + bvv, acc[i][5] + bvv, acc[i][6] + bvv, acc[i][7] + bvv);
        *(float4*)(crow)     = o0;
        *(float4*)(crow + 4) = o1;
    }
}

// ---------------- fused dots + softmax over T ----------------
// one block per (b, pixel); dots[t] = sum_ck g[b,p,ck] * xpatch[b,t,p,ck]; softmax over t
__global__ void __launch_bounds__(256) dots_softmax(
    const float* __restrict__ x, const float* __restrict__ g, float* __restrict__ attn)
{
    const int bp = blockIdx.x;
    const int b = bp >> 12, p = bp & 4095;
    const int h = p >> 6, w = p & 63;
    const float* grow = g + (size_t)bp * CK;
    const float* xb   = x + (size_t)b * (8UL * 256UL * HW);

    float acc[8] = {0, 0, 0, 0, 0, 0, 0, 0};
    for (int ck = threadIdx.x; ck < CK; ck += 256) {
        float gv = grow[ck];
        int c = ck / 9, j = ck - c * 9;
        int hi = h + j / 3 - 1;
        int wi = w + (j - (j / 3) * 3) - 1;
        if ((unsigned)hi < 64u && (unsigned)wi < 64u) {
            const float* xp = xb + (size_t)c * HW + hi * 64 + wi;
#pragma unroll
            for (int t = 0; t < 8; ++t) acc[t] += gv * xp[(size_t)t * (256UL * HW)];
        }
    }
#pragma unroll
    for (int t = 0; t < 8; ++t)
#pragma unroll
        for (int off = 16; off; off >>= 1) acc[t] += __shfl_down_sync(0xffffffffu, acc[t], off);

    __shared__ float red[8][8];
    const int lane = threadIdx.x & 31, wr = threadIdx.x >> 5;
    if (lane == 0) {
#pragma unroll
        for (int t = 0; t < 8; ++t) red[t][wr] = acc[t];
    }
    __syncthreads();
    if (threadIdx.x == 0) {
        float d[8];
#pragma unroll
        for (int t = 0; t < 8; ++t) {
            float s = 0.f;
#pragma unroll
            for (int q = 0; q < 8; ++q) s += red[t][q];
            d[t] = s;
        }
        float m = d[0];
#pragma unroll
        for (int t = 1; t < 8; ++t) m = fmaxf(m, d[t]);
        float e[8], ssum = 0.f;
#pragma unroll
        for (int t = 0; t < 8; ++t) { e[t] = __expf(d[t] - m); ssum += e[t]; }
        float inv = 1.f / ssum;
#pragma unroll
        for (int t = 0; t < 8; ++t) attn[(size_t)bp * 8 + t] = e[t] * inv;
    }
}

// ---------------- y[b, c*9+j, p] = sum_t attn[b,t,p] * xpatch ----------------
// block: (h, c0..c0+3, b); 256 threads = 4 channel groups x 64 pixels
__global__ void __launch_bounds__(256) weighted_patches(
    const float* __restrict__ x, const float* __restrict__ attn, float* __restrict__ y)
{
    const int h = blockIdx.x;
    const int c0 = blockIdx.y * 4;
    const int b = blockIdx.z;
    const int tid = threadIdx.x;
    const int lw = tid & 63, cg = tid >> 6;
    const int c = c0 + cg;

    __shared__ float xs[4][8][3][66];
    __shared__ float as[8][64];

    for (int idx = tid; idx < 512; idx += 256) {
        int ww = idx & 63, t = idx >> 6;
        as[t][ww] = attn[((size_t)b * HW + h * 64 + ww) * 8 + t];
    }
    for (int idx = tid; idx < 4 * 8 * 3 * 66; idx += 256) {
        int ci = idx / 1584;
        int r1 = idx - ci * 1584;
        int t = r1 / 198;
        int r2 = r1 - t * 198;
        int row = r2 / 66;
        int col = r2 - row * 66;
        int hi = h + row - 1, wi = col - 1;
        float v = 0.f;
        if ((unsigned)hi < 64u && (unsigned)wi < 64u)
            v = x[(((size_t)b * 8 + t) * 256 + c0 + ci) * HW + hi * 64 + wi];
        xs[ci][t][row][col] = v;
    }
    __syncthreads();

    float a[8];
#pragma unroll
    for (int t = 0; t < 8; ++t) a[t] = as[t][lw];

#pragma unroll
    for (int j = 0; j < 9; ++j) {
        int dy = j / 3, dx = j - dy * 3;
        float s = 0.f;
#pragma unroll
        for (int t = 0; t < 8; ++t) s += a[t] * xs[cg][t][dy][lw + dx];
        y[((size_t)b * CK + (c * 9 + j)) * HW + h * 64 + lw] = s;
    }
}

// ---------------- broadcast over T ----------------
__global__ void __launch_bounds__(256) bcast_out(const float4* __restrict__ ob, float4* __restrict__ out)
{
    const int i = blockIdx.x * 256 + threadIdx.x;   // 0 .. 1048575 (B*C*HW/4)
    float4 v = ob[i];
    const int b = i >> 18;            // / 262144
    const int r = i & 262143;
    const size_t base = ((size_t)b * 8) * 262144 + r;
#pragma unroll
    for (int t = 0; t < 8; ++t) out[base + (size_t)t * 262144] = v;
}

// ---------------- launch ----------------
extern "C" void kernel_launch(void* const* d_in, const int* in_sizes, int n_in,
                              void* d_out, int out_size)
{
    const float* x     = (const float*)d_in[0];
    const float* w_k   = (const float*)d_in[1];
    const float* w_q   = (const float*)d_in[2];
    const float* w_v   = (const float*)d_in[3];
    const float* w_out = (const float*)d_in[4];
    const float* b_out = (const float*)d_in[5];
    float* out = (float*)d_out;

    float *pk, *pg, *pa, *py, *pp, *po;
    cudaGetSymbolAddress((void**)&pk, g_k);
    cudaGetSymbolAddress((void**)&pg, g_g);
    cudaGetSymbolAddress((void**)&pa, g_attn);
    cudaGetSymbolAddress((void**)&py, g_y);
    cudaGetSymbolAddress((void**)&pp, g_pooled);
    cudaGetSymbolAddress((void**)&po, g_outb);

    // 1) k = conv(x[:,0], w_k): M=128, Cin=256, per batch
    conv3x3<<<dim3(32, 1, 4), 256>>>(w_k, x, pk, 128, 256,
                                     (long)8 * 256 * HW, (long)128 * HW, nullptr);

    // 2) g[b,p,ck] = sum_d k[b,d,p] * w_q[d,ck]   (M=HW, N=CK, K=DH)
    sgemm128<true><<<dim3(CK / 128, HW / 128, 4), 256>>>(
        pk, w_q, pg, HW, CK, 128,
        /*sAm*/ 1L, /*sAk*/ (long)HW, /*sBk*/ (long)CK,
        /*batchA*/ (long)128 * HW, /*batchB*/ 0L, /*batchC*/ (long)HW * CK, nullptr);

    // 3) dots + softmax -> attn
    dots_softmax<<<4 * HW, 256>>>(x, pg, pa);

    // 4) y = attn-weighted x patches
    weighted_patches<<<dim3(64, 64, 4), 256>>>(x, pa, py);

    // 5) pooled[b,d,p] = sum_ck w_v[d,ck] * y[b,ck,p]   (M=128, N=HW, K=CK)
    sgemm128<false><<<dim3(HW / 128, 1, 4), 256>>>(
        w_v, py, pp, 128, HW, CK,
        /*sAm*/ (long)CK, /*sAk*/ 1L, /*sBk*/ (long)HW,
        /*batchA*/ 0L, /*batchB*/ (long)CK * HW, /*batchC*/ (long)128 * HW, nullptr);

    // 6) out conv: M=256, Cin=128, + bias
    conv3x3<<<dim3(32, 2, 4), 256>>>(w_out, pp, po, 256, 128,
                                     (long)128 * HW, (long)256 * HW, b_out);

    // 7) broadcast over T
    bcast_out<<<4096, 256>>>((const float4*)po, (float4*)out);
}

// round 2
// speedup vs baseline: 1.0586x; 1.0586x over previous
#include <cuda_runtime.h>
#include <cstdint>

// Shapes (fixed): B=4, T=8, C=256, H=W=64 (HW=4096), DH=128, CK=C*9=2304
#define HW 4096
#define CK 2304
typedef unsigned long long u64;

// ---------------- scratch (device globals; allocation-free) ----------------
__device__ float g_k[4 * 128 * HW];        // k conv result
__device__ float g_gT[4 * CK * HW];        // g transposed: [b][ck][p]  (151 MB)
__device__ float g_attn[4 * 8 * HW];       // softmax weights [b][t][p]
__device__ float g_pooled[4 * 128 * HW];   // pooled
__device__ float g_outb[4 * 256 * HW];     // out conv per batch
__device__ float g_wvt[CK * 128];          // w_v transposed [ck][d]

// ---------------- packed f32x2 helpers ----------------
__device__ __forceinline__ u64 pack2(float v) {
    u64 r; asm("mov.b64 %0,{%1,%1};" : "=l"(r) : "f"(v)); return r;
}
__device__ __forceinline__ void ffma2(u64& d, u64 a, u64 b) {
    asm("fma.rn.f32x2 %0,%1,%2,%0;" : "+l"(d) : "l"(a), "l"(b));
}
__device__ __forceinline__ float2 unpk(u64 v) {
    float2 f; asm("mov.b64 {%0,%1},%2;" : "=f"(f.x), "=f"(f.y) : "l"(v)); return f;
}

// 8x8 outputs per thread, one k-step: As row (m-dim), Bs row (n-dim)
#define MICRO_STEP(ASROW, BSROW, ACC) do {                                   \
    float4 _a0 = *(const float4*)&(ASROW)[ty * 8];                           \
    float4 _a1 = *(const float4*)&(ASROW)[ty * 8 + 4];                       \
    const u64* _bp = (const u64*)&(BSROW)[tx * 8];                           \
    u64 _b0 = _bp[0], _b1 = _bp[1], _b2 = _bp[2], _b3 = _bp[3];              \
    float _av[8] = {_a0.x, _a0.y, _a0.z, _a0.w, _a1.x, _a1.y, _a1.z, _a1.w}; \
    _Pragma("unroll")                                                        \
    for (int _i = 0; _i < 8; ++_i) {                                         \
        u64 _ai = pack2(_av[_i]);                                            \
        ffma2((ACC)[_i][0], _ai, _b0); ffma2((ACC)[_i][1], _ai, _b1);        \
        ffma2((ACC)[_i][2], _ai, _b2); ffma2((ACC)[_i][3], _ai, _b3);        \
    }                                                                        \
} while (0)

// ---------------- 3x3 conv as implicit GEMM, FFMA2 + prefetch ----------------
// W: [M][Cin*9] row-major; X: [Cin][64][64] per batch; out: [M][4096]
__global__ void __launch_bounds__(256) conv3x3_f2(
    const float* __restrict__ W, const float* __restrict__ X, float* __restrict__ Cout,
    int M, int Cin, long bsX, long bsC, const float* __restrict__ bias)
{
    __shared__ __align__(16) float As[8][132];   // padded: conflict-free STS
    __shared__ __align__(16) float Bs[8][128];

    const int K = Cin * 9;
    const float* Xb = X + (size_t)blockIdx.z * bsX;
    float*       Cb = Cout + (size_t)blockIdx.z * bsC;
    const int bm = blockIdx.y * 128, bn = blockIdx.x * 128;
    const int tid = threadIdx.x, tx = tid & 15, ty = tid >> 4;
    const int am = tid >> 3, ak = tid & 7;          // A-tile mapping
    const int bk = tid >> 7, nn = tid & 127;        // B-tile mapping
    const int p = bn + nn, hh = p >> 6, ww = p & 63;

    u64 acc[8][4];
#pragma unroll
    for (int i = 0; i < 8; ++i)
#pragma unroll
        for (int j = 0; j < 4; ++j) acc[i][j] = 0ULL;

    float pa[4], pb[4];

    auto ldA = [&](int k0) {
#pragma unroll
        for (int r = 0; r < 4; ++r)
            pa[r] = W[(size_t)(bm + am + 32 * r) * K + k0 + ak];
    };
    auto ldB = [&](int k0) {
#pragma unroll
        for (int r = 0; r < 4; ++r) {
            int kb = k0 + bk + 2 * r;
            int c = kb / 9, j = kb - c * 9;
            int dy = j / 3, dx = j - dy * 3;
            int hi = hh + dy - 1, wi = ww + dx - 1;
            float v = 0.f;
            if ((unsigned)hi < 64u && (unsigned)wi < 64u)
                v = Xb[(size_t)c * HW + hi * 64 + wi];
            pb[r] = v;
        }
    };

    ldA(0); ldB(0);
    for (int k0 = 0; k0 < K; k0 += 8) {
        __syncthreads();
#pragma unroll
        for (int r = 0; r < 4; ++r) {
            As[ak][am + 32 * r] = pa[r];
            Bs[bk + 2 * r][nn] = pb[r];
        }
        __syncthreads();
        if (k0 + 8 < K) { ldA(k0 + 8); ldB(k0 + 8); }
#pragma unroll
        for (int kk = 0; kk < 8; ++kk) MICRO_STEP(As[kk], Bs[kk], acc);
    }

#pragma unroll
    for (int i = 0; i < 8; ++i) {
        int m = bm + ty * 8 + i;
        float bvv = bias ? bias[m] : 0.f;
        float2 u0 = unpk(acc[i][0]), u1 = unpk(acc[i][1]);
        float2 u2 = unpk(acc[i][2]), u3 = unpk(acc[i][3]);
        float* crow = Cb + (size_t)m * HW + bn + tx * 8;
        *(float4*)(crow)     = make_float4(u0.x + bvv, u0.y + bvv, u1.x + bvv, u1.y + bvv);
        *(float4*)(crow + 4) = make_float4(u2.x + bvv, u2.y + bvv, u3.x + bvv, u3.y + bvv);
    }
}

// ---------------- step2 GEMM: gT[ck][p] = sum_d w_q[d][ck] * k[d][p] ----------------
// A[m,k] = A[m + k*sAk] (m contiguous); B[k,n] = Bb[k*HW + n]; C ld = N=HW
__global__ void __launch_bounds__(256) sgemm_f2(
    const float* __restrict__ A, const float* __restrict__ B, float* __restrict__ C,
    int K, long sAk, long batchB, long batchC)
{
    __shared__ __align__(16) float As[8][128];
    __shared__ __align__(16) float Bs[8][128];

    const float* Bb = B + (size_t)blockIdx.z * batchB;
    float*       Cb = C + (size_t)blockIdx.z * batchC;
    const int bm = blockIdx.y * 128, bn = blockIdx.x * 128;
    const int tid = threadIdx.x, tx = tid & 15, ty = tid >> 4;
    const int kk0 = tid >> 7, nn = tid & 127;

    u64 acc[8][4];
#pragma unroll
    for (int i = 0; i < 8; ++i)
#pragma unroll
        for (int j = 0; j < 4; ++j) acc[i][j] = 0ULL;

    float pa[4], pb[4];
    auto ld = [&](int k0) {
#pragma unroll
        for (int r = 0; r < 4; ++r) {
            pa[r] = A[(size_t)(bm + nn) + (size_t)(k0 + kk0 + 2 * r) * sAk];
            pb[r] = Bb[(size_t)(k0 + kk0 + 2 * r) * HW + bn + nn];
        }
    };

    ld(0);
    for (int k0 = 0; k0 < K; k0 += 8) {
        __syncthreads();
#pragma unroll
        for (int r = 0; r < 4; ++r) {
            As[kk0 + 2 * r][nn] = pa[r];
            Bs[kk0 + 2 * r][nn] = pb[r];
        }
        __syncthreads();
        if (k0 + 8 < K) ld(k0 + 8);
#pragma unroll
        for (int kk = 0; kk < 8; ++kk) MICRO_STEP(As[kk], Bs[kk], acc);
    }

#pragma unroll
    for (int i = 0; i < 8; ++i) {
        float2 u0 = unpk(acc[i][0]), u1 = unpk(acc[i][1]);
        float2 u2 = unpk(acc[i][2]), u3 = unpk(acc[i][3]);
        float* crow = Cb + (size_t)(bm + ty * 8 + i) * HW + bn + tx * 8;
        *(float4*)(crow)     = make_float4(u0.x, u0.y, u1.x, u1.y);
        *(float4*)(crow + 4) = make_float4(u2.x, u2.y, u3.x, u3.y);
    }
}

// ---------------- fused dots + softmax (coalesced, row-based) ----------------
// grid (64 h, 4 b), 256 threads. Thread: p = tid&63, owns t=tg and t=tg+4.
__global__ void __launch_bounds__(256) dots_softmax2(
    const float* __restrict__ x, const float* __restrict__ gT, float* __restrict__ attn)
{
    const int h = blockIdx.x, b = blockIdx.y;
    const int tid = threadIdx.x, lane = tid & 31, wid = tid >> 5;
    const int p = tid & 63, tg = tid >> 6;

    __shared__ float xs[8][3][68];
    __shared__ float gs[9][64];
    __shared__ float dsm[8][64];

    const float* xb = x + (size_t)b * 8 * 256 * HW;
    const float* gb = gT + (size_t)b * CK * HW + h * 64;

    float acc0 = 0.f, acc1 = 0.f;
    for (int c = 0; c < 256; ++c) {
        __syncthreads();
        // x rows h-1..h+1 for t = wid (one warp per t)
        {
            const float* xr = xb + ((size_t)wid * 256 + c) * HW;
#pragma unroll
            for (int row = 0; row < 3; ++row) {
                int gh = h - 1 + row;
#pragma unroll
                for (int seg = 0; seg < 3; ++seg) {
                    int col = lane + seg * 32;
                    if (col < 66) {
                        int gw = col - 1;
                        float v = 0.f;
                        if ((unsigned)gh < 64u && (unsigned)gw < 64u)
                            v = xr[gh * 64 + gw];
                        xs[wid][row][col] = v;
                    }
                }
            }
        }
        // gT rows c*9..c*9+8 (64 pixels each), coalesced
        {
            int j = tid >> 6;
            gs[j][p]     = gb[(size_t)(c * 9 + j) * HW + p];
            gs[j + 4][p] = gb[(size_t)(c * 9 + j + 4) * HW + p];
            if (tid < 64) gs[8][tid] = gb[(size_t)(c * 9 + 8) * HW + tid];
        }
        __syncthreads();
#pragma unroll
        for (int dy = 0; dy < 3; ++dy)
#pragma unroll
            for (int dx = 0; dx < 3; ++dx) {
                float gv = gs[dy * 3 + dx][p];
                acc0 += gv * xs[tg][dy][p + dx];
                acc1 += gv * xs[tg + 4][dy][p + dx];
            }
    }
    __syncthreads();
    dsm[tg][p] = acc0; dsm[tg + 4][p] = acc1;
    __syncthreads();
    if (tid < 64) {
        float d[8], m = -1e30f;
#pragma unroll
        for (int t = 0; t < 8; ++t) { d[t] = dsm[t][tid]; m = fmaxf(m, d[t]); }
        float s = 0.f;
#pragma unroll
        for (int t = 0; t < 8; ++t) { d[t] = __expf(d[t] - m); s += d[t]; }
        float inv = 1.f / s;
#pragma unroll
        for (int t = 0; t < 8; ++t)
            attn[((size_t)(b * 8 + t)) * HW + h * 64 + tid] = d[t] * inv;
    }
}

// ---------------- fused v-GEMM: pooled = Wv * (attn-weighted patches) ----------------
// B-tile (y) generated in smem per K-step; eliminates the y round-trip entirely.
// grid (32 px-tiles, 4 b); tile 128 d x 128 px (2 image rows).
__global__ void __launch_bounds__(256, 1) pooled_fused(
    const float* __restrict__ x, const float* __restrict__ attn,
    const float* __restrict__ Wvt, float* __restrict__ pooled)
{
    const int bx = blockIdx.x, b = blockIdx.y;
    const int r0 = bx * 2;                                  // image rows r0, r0+1
    const int tid = threadIdx.x, lane = tid & 31, wid = tid >> 5;
    const int tx = tid & 15, ty = tid >> 4;

    __shared__ float attn_s[8][128];
    __shared__ __align__(16) float Ws[9][128];
    __shared__ float xs[8][4][68];
    __shared__ __align__(16) float ys[9][128];

    u64 acc[8][4];
#pragma unroll
    for (int i = 0; i < 8; ++i)
#pragma unroll
        for (int j = 0; j < 4; ++j) acc[i][j] = 0ULL;

    // attn once: [t][p] for this 128-pixel tile
#pragma unroll
    for (int l = 0; l < 4; ++l) {
        int idx = tid + l * 256, t = idx >> 7, pp = idx & 127;
        attn_s[t][pp] = attn[((size_t)(b * 8 + t)) * HW + r0 * 64 + pp];
    }

    float prx[12], prw[5];
    auto ldx = [&](int c) {   // warp wid -> t = wid; 4 rows (r0-1..r0+2) x 66 cols
        const float* xr = x + (((size_t)b * 8 + wid) * 256 + c) * HW;
#pragma unroll
        for (int row = 0; row < 4; ++row) {
            int gh = r0 - 1 + row;
#pragma unroll
            for (int seg = 0; seg < 3; ++seg) {
                int col = lane + seg * 32;
                float v = 0.f;
                if (col < 66 && (unsigned)gh < 64u) {
                    int gw = col - 1;
                    if ((unsigned)gw < 64u) v = xr[gh * 64 + gw];
                }
                prx[row * 3 + seg] = v;
            }
        }
    };
    auto ldw = [&](int c) {   // Wvt rows c*9..c*9+8: 1152 contiguous floats
        const float* wr = Wvt + (size_t)(c * 9) * 128;
#pragma unroll
        for (int l = 0; l < 5; ++l) {
            int idx = tid + l * 256;
            if (idx < 1152) prw[l] = wr[idx];
        }
    };

    ldx(0); ldw(0);
    for (int c = 0; c < 256; ++c) {
        __syncthreads();   // prior GEMM/ygen reads done
        // STS staged tiles
#pragma unroll
        for (int row = 0; row < 4; ++row)
#pragma unroll
            for (int seg = 0; seg < 3; ++seg) {
                int col = lane + seg * 32;
                if (col < 66) xs[wid][row][col] = prx[row * 3 + seg];
            }
#pragma unroll
        for (int l = 0; l < 5; ++l) {
            int idx = tid + l * 256;
            if (idx < 1152) Ws[idx >> 7][idx & 127] = prw[l];
        }
        __syncthreads();
        if (c + 1 < 256) { ldx(c + 1); ldw(c + 1); }
        // generate y-tile: ys[j][p] = sum_t attn[t][p] * xpatch
#pragma unroll
        for (int l = 0; l < 5; ++l) {
            int idx = tid + l * 256;
            if (idx < 1152) {
                int j = idx >> 7, pp = idx & 127;
                int dy = j / 3, dx = j - dy * 3;
                int hh = pp >> 6, w = pp & 63;
                float s = 0.f;
#pragma unroll
                for (int t = 0; t < 8; ++t)
                    s += attn_s[t][pp] * xs[t][hh + dy][w + dx];
                ys[j][pp] = s;
            }
        }
        __syncthreads();
        // 9-step GEMM: acc[d][p] += Ws[j][d] * ys[j][p]
#pragma unroll
        for (int kk = 0; kk < 9; ++kk) MICRO_STEP(Ws[kk], ys[kk], acc);
    }

#pragma unroll
    for (int i = 0; i < 8; ++i) {
        float2 u0 = unpk(acc[i][0]), u1 = unpk(acc[i][1]);
        float2 u2 = unpk(acc[i][2]), u3 = unpk(acc[i][3]);
        float* crow = pooled + (size_t)(b * 128 + ty * 8 + i) * HW + bx * 128 + tx * 8;
        *(float4*)(crow)     = make_float4(u0.x, u0.y, u1.x, u1.y);
        *(float4*)(crow + 4) = make_float4(u2.x, u2.y, u3.x, u3.y);
    }
}

// ---------------- w_v transpose: [128][2304] -> [2304][128] ----------------
__global__ void __launch_bounds__(256) transpose_wv(
    const float* __restrict__ wv, float* __restrict__ wvt)
{
    __shared__ float t[32][33];
    const int bx = blockIdx.x;   // ck tile (72)
    const int by = blockIdx.y;   // d tile (4)
    const int lx = threadIdx.x & 31, ly = threadIdx.x >> 5;  // 32 x 8
#pragma unroll
    for (int r = 0; r < 32; r += 8)
        t[ly + r][lx] = wv[(size_t)(by * 32 + ly + r) * CK + bx * 32 + lx];
    __syncthreads();
#pragma unroll
    for (int r = 0; r < 32; r += 8)
        wvt[(size_t)(bx * 32 + ly + r) * 128 + by * 32 + lx] = t[lx][ly + r];
}

// ---------------- broadcast over T ----------------
__global__ void __launch_bounds__(256) bcast_out(const float4* __restrict__ ob, float4* __restrict__ out)
{
    const int i = blockIdx.x * 256 + threadIdx.x;   // B*C*HW/4 = 1048576
    float4 v = ob[i];
    const int b = i >> 18;
    const int r = i & 262143;
    const size_t base = ((size_t)b * 8) * 262144 + r;
#pragma unroll
    for (int t = 0; t < 8; ++t) out[base + (size_t)t * 262144] = v;
}

// ---------------- launch ----------------
extern "C" void kernel_launch(void* const* d_in, const int* in_sizes, int n_in,
                              void* d_out, int out_size)
{
    const float* x     = (const float*)d_in[0];
    const float* w_k   = (const float*)d_in[1];
    const float* w_q   = (const float*)d_in[2];
    const float* w_v   = (const float*)d_in[3];
    const float* w_out = (const float*)d_in[4];
    const float* b_out = (const float*)d_in[5];
    float* out = (float*)d_out;

    float *pk, *pg, *pa, *pp, *po, *pwvt;
    cudaGetSymbolAddress((void**)&pk, g_k);
    cudaGetSymbolAddress((void**)&pg, g_gT);
    cudaGetSymbolAddress((void**)&pa, g_attn);
    cudaGetSymbolAddress((void**)&pp, g_pooled);
    cudaGetSymbolAddress((void**)&po, g_outb);
    cudaGetSymbolAddress((void**)&pwvt, g_wvt);

    // 0) transpose w_v -> [ck][d]
    transpose_wv<<<dim3(72, 4), 256>>>(w_v, pwvt);

    // 1) k = conv(x[:,0], w_k): M=128, Cin=256
    conv3x3_f2<<<dim3(32, 1, 4), 256>>>(w_k, x, pk, 128, 256,
                                        (long)8 * 256 * HW, (long)128 * HW, nullptr);

    // 2) gT[b][ck][p] = sum_d w_q[d][ck] * k[b][d][p]   (M=CK, N=HW, K=128)
    sgemm_f2<<<dim3(32, CK / 128, 4), 256>>>(w_q, pk, pg, 128,
                                             (long)CK, (long)128 * HW, (long)CK * HW);

    // 3) dots + softmax -> attn [b][t][p]
    dots_softmax2<<<dim3(64, 4), 256>>>(x, pg, pa);

    // 4+5) fused: pooled = Wv * (attn-weighted patches), y generated in smem
    pooled_fused<<<dim3(32, 4), 256>>>(x, pa, pwvt, pp);

    // 6) out conv: M=256, Cin=128, + bias
    conv3x3_f2<<<dim3(32, 2, 4), 256>>>(w_out, pp, po, 256, 128,
                                        (long)128 * HW, (long)256 * HW, b_out);

    // 7) broadcast over T
    bcast_out<<<4096, 256>>>((const float4*)po, (float4*)out);
}

// round 3
// speedup vs baseline: 1.3198x; 1.2467x over previous
#include <cuda_runtime.h>
#include <cstdint>

// Shapes (fixed): B=4, T=8, C=256, H=W=64 (HW=4096), DH=128, CK=C*9=2304
#define HW 4096
#define CK 2304
typedef unsigned long long u64;

// ---------------- scratch (device globals; allocation-free) ----------------
__device__ float g_k[4 * 128 * HW];          // k conv result
__device__ float g_gT[4 * CK * HW];          // g transposed: [b][ck][p]
__device__ float g_dpart[4 * 8 * 8 * HW];    // partial dots [b][cs][t][p]
__device__ float g_attn[4 * 8 * HW];         // softmax weights [b][t][p]
__device__ float g_pooled[4 * 128 * HW];     // pooled
__device__ float g_wvt[CK * 128];            // w_v transposed [ck][d]

// ---------------- packed f32x2 helpers ----------------
__device__ __forceinline__ u64 pack2(float v) {
    u64 r; asm("mov.b64 %0,{%1,%1};" : "=l"(r) : "f"(v)); return r;
}
__device__ __forceinline__ void ffma2(u64& d, u64 a, u64 b) {
    asm("fma.rn.f32x2 %0,%1,%2,%0;" : "+l"(d) : "l"(a), "l"(b));
}
__device__ __forceinline__ float2 unpk(u64 v) {
    float2 f; asm("mov.b64 {%0,%1},%2;" : "=f"(f.x), "=f"(f.y) : "l"(v)); return f;
}

// 8x8 outputs per thread, one k-step
#define MICRO_STEP(ASROW, BSROW, ACC) do {                                   \
    float4 _a0 = *(const float4*)&(ASROW)[ty * 8];                           \
    float4 _a1 = *(const float4*)&(ASROW)[ty * 8 + 4];                       \
    const u64* _bp = (const u64*)&(BSROW)[tx * 8];                           \
    u64 _b0 = _bp[0], _b1 = _bp[1], _b2 = _bp[2], _b3 = _bp[3];              \
    float _av[8] = {_a0.x, _a0.y, _a0.z, _a0.w, _a1.x, _a1.y, _a1.z, _a1.w}; \
    _Pragma("unroll")                                                        \
    for (int _i = 0; _i < 8; ++_i) {                                         \
        u64 _ai = pack2(_av[_i]);                                            \
        ffma2((ACC)[_i][0], _ai, _b0); ffma2((ACC)[_i][1], _ai, _b1);        \
        ffma2((ACC)[_i][2], _ai, _b2); ffma2((ACC)[_i][3], _ai, _b3);        \
    }                                                                        \
} while (0)

// ---------------- 3x3 conv as implicit GEMM, FFMA2 + double buffer ----------------
// W: [M][Cin*9] row-major; X: [Cin][64][64] per batch; out [M][4096] or bcast to d_out
template <bool BCAST>
__global__ void __launch_bounds__(256) conv3x3_f2(
    const float* __restrict__ W, const float* __restrict__ X, float* __restrict__ Cout,
    int M, int Cin, long bsX, long bsC, const float* __restrict__ bias)
{
    __shared__ __align__(16) float As[2][8][132];
    __shared__ __align__(16) float Bs[2][8][128];

    const int K = Cin * 9;
    const float* Xb = X + (size_t)blockIdx.z * bsX;
    const int bm = blockIdx.y * 128, bn = blockIdx.x * 128;
    const int tid = threadIdx.x, tx = tid & 15, ty = tid >> 4;
    const int am = tid >> 3, ak = tid & 7;          // A-tile mapping
    const int bk = tid >> 7, nn = tid & 127;        // B-tile mapping
    const int p = bn + nn, hh = p >> 6, ww = p & 63;

    u64 acc[8][4];
#pragma unroll
    for (int i = 0; i < 8; ++i)
#pragma unroll
        for (int j = 0; j < 4; ++j) acc[i][j] = 0ULL;

    float pa[4], pb[4];
    auto ldA = [&](int k0) {
#pragma unroll
        for (int r = 0; r < 4; ++r)
            pa[r] = W[(size_t)(bm + am + 32 * r) * K + k0 + ak];
    };
    auto ldB = [&](int k0) {
#pragma unroll
        for (int r = 0; r < 4; ++r) {
            int kb = k0 + bk + 2 * r;
            int c = kb / 9, j = kb - c * 9;
            int dy = j / 3, dx = j - dy * 3;
            int hi = hh + dy - 1, wi = ww + dx - 1;
            float v = 0.f;
            if ((unsigned)hi < 64u && (unsigned)wi < 64u)
                v = Xb[(size_t)c * HW + hi * 64 + wi];
            pb[r] = v;
        }
    };
    auto sts = [&](int buf) {
#pragma unroll
        for (int r = 0; r < 4; ++r) {
            As[buf][ak][am + 32 * r] = pa[r];
            Bs[buf][bk + 2 * r][nn] = pb[r];
        }
    };

    const int nIter = K >> 3;
    ldA(0); ldB(0);
    sts(0);
    __syncthreads();
    for (int it = 0; it < nIter; ++it) {
        const int cur = it & 1;
        if (it + 1 < nIter) { ldA((it + 1) * 8); ldB((it + 1) * 8); }
#pragma unroll
        for (int kk = 0; kk < 8; ++kk) MICRO_STEP(As[cur][kk], Bs[cur][kk], acc);
        if (it + 1 < nIter) sts(cur ^ 1);
        __syncthreads();
    }

#pragma unroll
    for (int i = 0; i < 8; ++i) {
        int m = bm + ty * 8 + i;
        float bvv = bias ? bias[m] : 0.f;
        float2 u0 = unpk(acc[i][0]), u1 = unpk(acc[i][1]);
        float2 u2 = unpk(acc[i][2]), u3 = unpk(acc[i][3]);
        float4 o0 = make_float4(u0.x + bvv, u0.y + bvv, u1.x + bvv, u1.y + bvv);
        float4 o1 = make_float4(u2.x + bvv, u2.y + bvv, u3.x + bvv, u3.y + bvv);
        if (BCAST) {
            // write all 8 frames: out[b][t][m][p]
            const int b = blockIdx.z;
#pragma unroll
            for (int t = 0; t < 8; ++t) {
                float* crow = Cout + (((size_t)(b * 8 + t)) * 256 + m) * HW + bn + tx * 8;
                *(float4*)(crow)     = o0;
                *(float4*)(crow + 4) = o1;
            }
        } else {
            float* crow = Cout + (size_t)blockIdx.z * bsC + (size_t)m * HW + bn + tx * 8;
            *(float4*)(crow)     = o0;
            *(float4*)(crow + 4) = o1;
        }
    }
}

// ---------------- step2 GEMM (double-buffered): gT[ck][p] = sum_d w_q[d][ck]*k[d][p] ----------------
__global__ void __launch_bounds__(256) sgemm_f2(
    const float* __restrict__ A, const float* __restrict__ B, float* __restrict__ C,
    int K, long sAk, long batchB, long batchC)
{
    __shared__ __align__(16) float As[2][8][128];
    __shared__ __align__(16) float Bs[2][8][128];

    const float* Bb = B + (size_t)blockIdx.z * batchB;
    float*       Cb = C + (size_t)blockIdx.z * batchC;
    const int bm = blockIdx.y * 128, bn = blockIdx.x * 128;
    const int tid = threadIdx.x, tx = tid & 15, ty = tid >> 4;
    const int kk0 = tid >> 7, nn = tid & 127;

    u64 acc[8][4];
#pragma unroll
    for (int i = 0; i < 8; ++i)
#pragma unroll
        for (int j = 0; j < 4; ++j) acc[i][j] = 0ULL;

    float pa[4], pb[4];
    auto ld = [&](int k0) {
#pragma unroll
        for (int r = 0; r < 4; ++r) {
            pa[r] = A[(size_t)(bm + nn) + (size_t)(k0 + kk0 + 2 * r) * sAk];
            pb[r] = Bb[(size_t)(k0 + kk0 + 2 * r) * HW + bn + nn];
        }
    };
    auto sts = [&](int buf) {
#pragma unroll
        for (int r = 0; r < 4; ++r) {
            As[buf][kk0 + 2 * r][nn] = pa[r];
            Bs[buf][kk0 + 2 * r][nn] = pb[r];
        }
    };

    const int nIter = K >> 3;
    ld(0);
    sts(0);
    __syncthreads();
    for (int it = 0; it < nIter; ++it) {
        const int cur = it & 1;
        if (it + 1 < nIter) ld((it + 1) * 8);
#pragma unroll
        for (int kk = 0; kk < 8; ++kk) MICRO_STEP(As[cur][kk], Bs[cur][kk], acc);
        if (it + 1 < nIter) sts(cur ^ 1);
        __syncthreads();
    }

#pragma unroll
    for (int i = 0; i < 8; ++i) {
        float2 u0 = unpk(acc[i][0]), u1 = unpk(acc[i][1]);
        float2 u2 = unpk(acc[i][2]), u3 = unpk(acc[i][3]);
        float* crow = Cb + (size_t)(bm + ty * 8 + i) * HW + bn + tx * 8;
        *(float4*)(crow)     = make_float4(u0.x, u0.y, u1.x, u1.y);
        *(float4*)(crow + 4) = make_float4(u2.x, u2.y, u3.x, u3.y);
    }
}

// ---------------- dots, channel-split: 2048 blocks ----------------
// grid (h=64, cs=8, b=4), 256 thr. Block handles 32 channels -> partial dots.
__global__ void __launch_bounds__(256) dots_split(
    const float* __restrict__ x, const float* __restrict__ gT, float* __restrict__ dpart)
{
    const int h = blockIdx.x, cs = blockIdx.y, b = blockIdx.z;
    const int tid = threadIdx.x, lane = tid & 31, wid = tid >> 5;
    const int p = tid & 63, tg = tid >> 6;

    __shared__ float xs[8][4][3][68];   // [t][ch][row][col]
    __shared__ float gs[36][64];        // [ch*9+j][p]

    const float* xb = x + (size_t)b * 8 * 256 * HW;
    const float* gb = gT + (size_t)b * CK * HW + h * 64;

    float acc0 = 0.f, acc1 = 0.f;
    for (int cg = 0; cg < 8; ++cg) {
        const int c0 = cs * 32 + cg * 4;
        __syncthreads();
        // x: warp wid -> t = wid; 4 channels x 3 rows x 66 cols
        {
            const float* xt = xb + (size_t)wid * 256 * HW;
#pragma unroll
            for (int ch = 0; ch < 4; ++ch) {
                const float* xr = xt + (size_t)(c0 + ch) * HW;
#pragma unroll
                for (int row = 0; row < 3; ++row) {
                    int gh = h - 1 + row;
#pragma unroll
                    for (int seg = 0; seg < 3; ++seg) {
                        int col = lane + seg * 32;
                        if (col < 66) {
                            int gw = col - 1;
                            float v = 0.f;
                            if ((unsigned)gh < 64u && (unsigned)gw < 64u)
                                v = xr[gh * 64 + gw];
                            xs[wid][ch][row][col] = v;
                        }
                    }
                }
            }
        }
        // g: 36 rows x 64 cols, coalesced
#pragma unroll
        for (int l = 0; l < 9; ++l) {
            int idx = tid + l * 256;
            int row = idx >> 6, col = idx & 63;
            int ch = row / 9, j = row - ch * 9;
            gs[row][col] = gb[(size_t)((c0 + ch) * 9 + j) * HW + col];
        }
        __syncthreads();
#pragma unroll
        for (int ch = 0; ch < 4; ++ch)
#pragma unroll
            for (int dy = 0; dy < 3; ++dy)
#pragma unroll
                for (int dx = 0; dx < 3; ++dx) {
                    float gv = gs[ch * 9 + dy * 3 + dx][p];
                    acc0 += gv * xs[tg][ch][dy][p + dx];
                    acc1 += gv * xs[tg + 4][ch][dy][p + dx];
                }
    }
    // dpart[b][cs][t][p]
    dpart[(((size_t)b * 8 + cs) * 8 + tg)     * HW + h * 64 + p] = acc0;
    dpart[(((size_t)b * 8 + cs) * 8 + tg + 4) * HW + h * 64 + p] = acc1;
}

// ---------------- reduce partials + softmax ----------------
__global__ void __launch_bounds__(256) dots_reduce(
    const float* __restrict__ dpart, float* __restrict__ attn)
{
    const int g = blockIdx.x * 256 + threadIdx.x;   // 16384 = 4b * 4096p
    const int b = g >> 12, p = g & 4095;
    float d[8];
#pragma unroll
    for (int t = 0; t < 8; ++t) d[t] = 0.f;
#pragma unroll
    for (int cs = 0; cs < 8; ++cs)
#pragma unroll
        for (int t = 0; t < 8; ++t)
            d[t] += dpart[(((size_t)b * 8 + cs) * 8 + t) * HW + p];
    float m = d[0];
#pragma unroll
    for (int t = 1; t < 8; ++t) m = fmaxf(m, d[t]);
    float s = 0.f;
#pragma unroll
    for (int t = 0; t < 8; ++t) { d[t] = __expf(d[t] - m); s += d[t]; }
    float inv = 1.f / s;
#pragma unroll
    for (int t = 0; t < 8; ++t)
        attn[((size_t)(b * 8 + t)) * HW + p] = d[t] * inv;
}

// ---------------- fused v-GEMM: pooled = Wv * (attn-weighted patches) ----------------
__global__ void __launch_bounds__(256, 1) pooled_fused(
    const float* __restrict__ x, const float* __restrict__ attn,
    const float* __restrict__ Wvt, float* __restrict__ pooled)
{
    const int bx = blockIdx.x, b = blockIdx.y;
    const int r0 = bx * 2;
    const int tid = threadIdx.x, lane = tid & 31, wid = tid >> 5;
    const int tx = tid & 15, ty = tid >> 4;

    __shared__ float attn_s[8][128];
    __shared__ __align__(16) float Ws[9][128];
    __shared__ float xs[8][4][68];
    __shared__ __align__(16) float ys[9][128];

    u64 acc[8][4];
#pragma unroll
    for (int i = 0; i < 8; ++i)
#pragma unroll
        for (int j = 0; j < 4; ++j) acc[i][j] = 0ULL;

#pragma unroll
    for (int l = 0; l < 4; ++l) {
        int idx = tid + l * 256, t = idx >> 7, pp = idx & 127;
        attn_s[t][pp] = attn[((size_t)(b * 8 + t)) * HW + r0 * 64 + pp];
    }

    float prx[12], prw[5];
    auto ldx = [&](int c) {
        const float* xr = x + (((size_t)b * 8 + wid) * 256 + c) * HW;
#pragma unroll
        for (int row = 0; row < 4; ++row) {
            int gh = r0 - 1 + row;
#pragma unroll
            for (int seg = 0; seg < 3; ++seg) {
                int col = lane + seg * 32;
                float v = 0.f;
                if (col < 66 && (unsigned)gh < 64u) {
                    int gw = col - 1;
                    if ((unsigned)gw < 64u) v = xr[gh * 64 + gw];
                }
                prx[row * 3 + seg] = v;
            }
        }
    };
    auto ldw = [&](int c) {
        const float* wr = Wvt + (size_t)(c * 9) * 128;
#pragma unroll
        for (int l = 0; l < 5; ++l) {
            int idx = tid + l * 256;
            if (idx < 1152) prw[l] = wr[idx];
        }
    };

    ldx(0); ldw(0);
    for (int c = 0; c < 256; ++c) {
        __syncthreads();
#pragma unroll
        for (int row = 0; row < 4; ++row)
#pragma unroll
            for (int seg = 0; seg < 3; ++seg) {
                int col = lane + seg * 32;
                if (col < 66) xs[wid][row][col] = prx[row * 3 + seg];
            }
#pragma unroll
        for (int l = 0; l < 5; ++l) {
            int idx = tid + l * 256;
            if (idx < 1152) Ws[idx >> 7][idx & 127] = prw[l];
        }
        __syncthreads();
        if (c + 1 < 256) { ldx(c + 1); ldw(c + 1); }
#pragma unroll
        for (int l = 0; l < 5; ++l) {
            int idx = tid + l * 256;
            if (idx < 1152) {
                int j = idx >> 7, pp = idx & 127;
                int dy = j / 3, dx = j - dy * 3;
                int hh = pp >> 6, w = pp & 63;
                float s = 0.f;
#pragma unroll
                for (int t = 0; t < 8; ++t)
                    s += attn_s[t][pp] * xs[t][hh + dy][w + dx];
                ys[j][pp] = s;
            }
        }
        __syncthreads();
#pragma unroll
        for (int kk = 0; kk < 9; ++kk) MICRO_STEP(Ws[kk], ys[kk], acc);
    }

#pragma unroll
    for (int i = 0; i < 8; ++i) {
        float2 u0 = unpk(acc[i][0]), u1 = unpk(acc[i][1]);
        float2 u2 = unpk(acc[i][2]), u3 = unpk(acc[i][3]);
        float* crow = pooled + (size_t)(b * 128 + ty * 8 + i) * HW + bx * 128 + tx * 8;
        *(float4*)(crow)     = make_float4(u0.x, u0.y, u1.x, u1.y);
        *(float4*)(crow + 4) = make_float4(u2.x, u2.y, u3.x, u3.y);
    }
}

// ---------------- w_v transpose: [128][2304] -> [2304][128] ----------------
__global__ void __launch_bounds__(256) transpose_wv(
    const float* __restrict__ wv, float* __restrict__ wvt)
{
    __shared__ float t[32][33];
    const int bx = blockIdx.x, by = blockIdx.y;
    const int lx = threadIdx.x & 31, ly = threadIdx.x >> 5;
#pragma unroll
    for (int r = 0; r < 32; r += 8)
        t[ly + r][lx] = wv[(size_t)(by * 32 + ly + r) * CK + bx * 32 + lx];
    __syncthreads();
#pragma unroll
    for (int r = 0; r < 32; r += 8)
        wvt[(size_t)(bx * 32 + ly + r) * 128 + by * 32 + lx] = t[lx][ly + r];
}

// ---------------- launch ----------------
extern "C" void kernel_launch(void* const* d_in, const int* in_sizes, int n_in,
                              void* d_out, int out_size)
{
    const float* x     = (const float*)d_in[0];
    const float* w_k   = (const float*)d_in[1];
    const float* w_q   = (const float*)d_in[2];
    const float* w_v   = (const float*)d_in[3];
    const float* w_out = (const float*)d_in[4];
    const float* b_out = (const float*)d_in[5];
    float* out = (float*)d_out;

    float *pk, *pg, *pdp, *pa, *pp, *pwvt;
    cudaGetSymbolAddress((void**)&pk, g_k);
    cudaGetSymbolAddress((void**)&pg, g_gT);
    cudaGetSymbolAddress((void**)&pdp, g_dpart);
    cudaGetSymbolAddress((void**)&pa, g_attn);
    cudaGetSymbolAddress((void**)&pp, g_pooled);
    cudaGetSymbolAddress((void**)&pwvt, g_wvt);

    // 0) transpose w_v -> [ck][d]
    transpose_wv<<<dim3(72, 4), 256>>>(w_v, pwvt);

    // 1) k = conv(x[:,0], w_k): M=128, Cin=256
    conv3x3_f2<false><<<dim3(32, 1, 4), 256>>>(w_k, x, pk, 128, 256,
                                               (long)8 * 256 * HW, (long)128 * HW, nullptr);

    // 2) gT[b][ck][p] = sum_d w_q[d][ck] * k[b][d][p]
    sgemm_f2<<<dim3(32, CK / 128, 4), 256>>>(w_q, pk, pg, 128,
                                             (long)CK, (long)128 * HW, (long)CK * HW);

    // 3a) partial dots (channel-split, 2048 blocks)
    dots_split<<<dim3(64, 8, 4), 256>>>(x, pg, pdp);
    // 3b) reduce + softmax
    dots_reduce<<<64, 256>>>(pdp, pa);

    // 4+5) fused: pooled = Wv * (attn-weighted patches)
    pooled_fused<<<dim3(32, 4), 256>>>(x, pa, pwvt, pp);

    // 6+7) out conv with bias, broadcast over T fused into epilogue
    conv3x3_f2<true><<<dim3(32, 2, 4), 256>>>(w_out, pp, out, 256, 128,
                                              (long)128 * HW, 0L, b_out);
}

// round 4
// speedup vs baseline: 1.3278x; 1.0061x over previous
#include <cuda_runtime.h>
#include <cstdint>

// Shapes (fixed): B=4, T=8, C=256, H=W=64 (HW=4096), DH=128, CK=C*9=2304
#define HW 4096
#define CK 2304
typedef unsigned long long u64;

// ---------------- scratch (device globals; allocation-free) ----------------
__device__ float g_k[8 * 128 * HW];          // k partials [b*2+cs][128][HW]
__device__ float g_gT[4 * CK * HW];          // g transposed: [b][ck][p]
__device__ float g_dpart[4 * 8 * 8 * HW];    // partial dots [b][cs][t][p]
__device__ float g_attn[4 * 8 * HW];         // softmax weights [b][t][p]
__device__ float g_ppart[8 * 128 * HW];      // pooled partials [b*2+cs][128][HW]
__device__ float g_wvt[CK * 128];            // w_v transposed [ck][d]

// ---------------- packed f32x2 helpers ----------------
__device__ __forceinline__ u64 pack2(float v) {
    u64 r; asm("mov.b64 %0,{%1,%1};" : "=l"(r) : "f"(v)); return r;
}
__device__ __forceinline__ void ffma2(u64& d, u64 a, u64 b) {
    asm("fma.rn.f32x2 %0,%1,%2,%0;" : "+l"(d) : "l"(a), "l"(b));
}
__device__ __forceinline__ float2 unpk(u64 v) {
    float2 f; asm("mov.b64 {%0,%1},%2;" : "=f"(f.x), "=f"(f.y) : "l"(v)); return f;
}

#define MICRO_STEP(ASROW, BSROW, ACC) do {                                   \
    float4 _a0 = *(const float4*)&(ASROW)[ty * 8];                           \
    float4 _a1 = *(const float4*)&(ASROW)[ty * 8 + 4];                       \
    const u64* _bp = (const u64*)&(BSROW)[tx * 8];                           \
    u64 _b0 = _bp[0], _b1 = _bp[1], _b2 = _bp[2], _b3 = _bp[3];              \
    float _av[8] = {_a0.x, _a0.y, _a0.z, _a0.w, _a1.x, _a1.y, _a1.z, _a1.w}; \
    _Pragma("unroll")                                                        \
    for (int _i = 0; _i < 8; ++_i) {                                         \
        u64 _ai = pack2(_av[_i]);                                            \
        ffma2((ACC)[_i][0], _ai, _b0); ffma2((ACC)[_i][1], _ai, _b1);        \
        ffma2((ACC)[_i][2], _ai, _b2); ffma2((ACC)[_i][3], _ai, _b3);        \
    }                                                                        \
} while (0)

// ---------------- 3x3 conv as implicit GEMM, FFMA2 + double buffer ----------------
// CS=2: channel-split halves (blockIdx.z = b*2+cs), partial outputs.
// SUM2: X element = Xb[i] + Xb2[i] (sum of two partial buffers).
// BCAST: write all 8 frames of d_out.
template <bool BCAST, bool SUM2, int CS>
__global__ void __launch_bounds__(256) conv3x3_f2(
    const float* __restrict__ W, const float* __restrict__ X, float* __restrict__ Cout,
    int M, int CinPer, long bsX, long bsC, const float* __restrict__ bias)
{
    __shared__ __align__(16) float As[2][8][132];
    __shared__ __align__(16) float Bs[2][8][128];

    const int K = CinPer * 9;
    const int Ktot = CS * K;
    const int z = blockIdx.z;
    const int b = (CS == 2) ? (z >> 1) : z;
    const int cs = (CS == 2) ? (z & 1) : 0;
    const float* Xb = X + (size_t)b * bsX + (size_t)cs * CinPer * HW;
    const float* Xb2 = Xb + (size_t)CinPer * HW;   // used if SUM2
    const float* Wb = W + (size_t)cs * K;

    const int bm = blockIdx.y * 128, bn = blockIdx.x * 128;
    const int tid = threadIdx.x, tx = tid & 15, ty = tid >> 4;
    const int am = tid >> 3, ak = tid & 7;
    const int bk = tid >> 7, nn = tid & 127;
    const int p = bn + nn, hh = p >> 6, ww = p & 63;

    u64 acc[8][4];
#pragma unroll
    for (int i = 0; i < 8; ++i)
#pragma unroll
        for (int j = 0; j < 4; ++j) acc[i][j] = 0ULL;

    float pa[4], pb[4];
    auto ldA = [&](int k0) {
#pragma unroll
        for (int r = 0; r < 4; ++r)
            pa[r] = Wb[(size_t)(bm + am + 32 * r) * Ktot + k0 + ak];
    };
    auto ldB = [&](int k0) {
#pragma unroll
        for (int r = 0; r < 4; ++r) {
            int kb = k0 + bk + 2 * r;
            int c = kb / 9, j = kb - c * 9;
            int dy = j / 3, dx = j - dy * 3;
            int hi = hh + dy - 1, wi = ww + dx - 1;
            float v = 0.f;
            if ((unsigned)hi < 64u && (unsigned)wi < 64u) {
                size_t off = (size_t)c * HW + hi * 64 + wi;
                v = Xb[off];
                if (SUM2) v += Xb2[off];
            }
            pb[r] = v;
        }
    };
    auto sts = [&](int buf) {
#pragma unroll
        for (int r = 0; r < 4; ++r) {
            As[buf][ak][am + 32 * r] = pa[r];
            Bs[buf][bk + 2 * r][nn] = pb[r];
        }
    };

    const int nIter = K >> 3;
    ldA(0); ldB(0);
    sts(0);
    __syncthreads();
    for (int it = 0; it < nIter; ++it) {
        const int cur = it & 1;
        if (it + 1 < nIter) { ldA((it + 1) * 8); ldB((it + 1) * 8); }
#pragma unroll
        for (int kk = 0; kk < 8; ++kk) MICRO_STEP(As[cur][kk], Bs[cur][kk], acc);
        if (it + 1 < nIter) sts(cur ^ 1);
        __syncthreads();
    }

#pragma unroll
    for (int i = 0; i < 8; ++i) {
        int m = bm + ty * 8 + i;
        float bvv = bias ? bias[m] : 0.f;
        float2 u0 = unpk(acc[i][0]), u1 = unpk(acc[i][1]);
        float2 u2 = unpk(acc[i][2]), u3 = unpk(acc[i][3]);
        float4 o0 = make_float4(u0.x + bvv, u0.y + bvv, u1.x + bvv, u1.y + bvv);
        float4 o1 = make_float4(u2.x + bvv, u2.y + bvv, u3.x + bvv, u3.y + bvv);
        if (BCAST) {
#pragma unroll
            for (int t = 0; t < 8; ++t) {
                float* crow = Cout + (((size_t)(b * 8 + t)) * 256 + m) * HW + bn + tx * 8;
                *(float4*)(crow)     = o0;
                *(float4*)(crow + 4) = o1;
            }
        } else {
            float* crow = Cout + (size_t)z * bsC + (size_t)m * HW + bn + tx * 8;
            *(float4*)(crow)     = o0;
            *(float4*)(crow + 4) = o1;
        }
    }
}

// ---------------- step2 GEMM: gT[ck][p] = sum_d w_q[d][ck] * (k0+k1)[d][p] ----------------
__global__ void __launch_bounds__(256) sgemm_f2(
    const float* __restrict__ A, const float* __restrict__ B, float* __restrict__ C,
    int K, long sAk, long batchB, long batchC)
{
    __shared__ __align__(16) float As[2][8][128];
    __shared__ __align__(16) float Bs[2][8][128];

    const float* Bb = B + (size_t)blockIdx.z * batchB;
    const float* Bb2 = Bb + (size_t)128 * HW;
    float*       Cb = C + (size_t)blockIdx.z * batchC;
    const int bm = blockIdx.y * 128, bn = blockIdx.x * 128;
    const int tid = threadIdx.x, tx = tid & 15, ty = tid >> 4;
    const int kk0 = tid >> 7, nn = tid & 127;

    u64 acc[8][4];
#pragma unroll
    for (int i = 0; i < 8; ++i)
#pragma unroll
        for (int j = 0; j < 4; ++j) acc[i][j] = 0ULL;

    float pa[4], pb[4];
    auto ld = [&](int k0) {
#pragma unroll
        for (int r = 0; r < 4; ++r) {
            size_t boff = (size_t)(k0 + kk0 + 2 * r) * HW + bn + nn;
            pa[r] = A[(size_t)(bm + nn) + (size_t)(k0 + kk0 + 2 * r) * sAk];
            pb[r] = Bb[boff] + Bb2[boff];
        }
    };
    auto sts = [&](int buf) {
#pragma unroll
        for (int r = 0; r < 4; ++r) {
            As[buf][kk0 + 2 * r][nn] = pa[r];
            Bs[buf][kk0 + 2 * r][nn] = pb[r];
        }
    };

    const int nIter = K >> 3;
    ld(0);
    sts(0);
    __syncthreads();
    for (int it = 0; it < nIter; ++it) {
        const int cur = it & 1;
        if (it + 1 < nIter) ld((it + 1) * 8);
#pragma unroll
        for (int kk = 0; kk < 8; ++kk) MICRO_STEP(As[cur][kk], Bs[cur][kk], acc);
        if (it + 1 < nIter) sts(cur ^ 1);
        __syncthreads();
    }

#pragma unroll
    for (int i = 0; i < 8; ++i) {
        float2 u0 = unpk(acc[i][0]), u1 = unpk(acc[i][1]);
        float2 u2 = unpk(acc[i][2]), u3 = unpk(acc[i][3]);
        float* crow = Cb + (size_t)(bm + ty * 8 + i) * HW + bn + tx * 8;
        *(float4*)(crow)     = make_float4(u0.x, u0.y, u1.x, u1.y);
        *(float4*)(crow + 4) = make_float4(u2.x, u2.y, u3.x, u3.y);
    }
}

// ---------------- dots, 2-row tiles + channel split: 1024 blocks ----------------
// grid (hp=32, cs=8, b=4), 256 thr. Block: rows 2hp..2hp+1 (128 px), 32 channels.
__global__ void __launch_bounds__(256) dots_split2(
    const float* __restrict__ x, const float* __restrict__ gT, float* __restrict__ dpart)
{
    const int hp = blockIdx.x, cs = blockIdx.y, b = blockIdx.z;
    const int tid = threadIdx.x, lane = tid & 31, wid = tid >> 5;
    const int p = tid & 127, ts = tid >> 7;          // ts in {0,1}; t = ts + 2*ti
    const int hl = p >> 6, w = p & 63;

    __shared__ float xs[8][4][4][68];   // [t][ch][row][col]
    __shared__ float gs[36][128];       // [ch*9+j][p]

    const float* xb = x + (size_t)b * 8 * 256 * HW;
    const float* gb = gT + (size_t)b * CK * HW + hp * 128;

    float acc[4] = {0.f, 0.f, 0.f, 0.f};
    for (int cg = 0; cg < 8; ++cg) {
        const int c0 = cs * 32 + cg * 4;
        __syncthreads();
        // x: warp wid -> t = wid; 4 channels x 4 rows (2hp-1..2hp+2) x 66 cols
        {
            const float* xt = xb + (size_t)wid * 256 * HW;
#pragma unroll
            for (int ch = 0; ch < 4; ++ch) {
                const float* xr = xt + (size_t)(c0 + ch) * HW;
#pragma unroll
                for (int row = 0; row < 4; ++row) {
                    int gh = 2 * hp - 1 + row;
#pragma unroll
                    for (int seg = 0; seg < 3; ++seg) {
                        int col = lane + seg * 32;
                        if (col < 66) {
                            int gw = col - 1;
                            float v = 0.f;
                            if ((unsigned)gh < 64u && (unsigned)gw < 64u)
                                v = xr[gh * 64 + gw];
                            xs[wid][ch][row][col] = v;
                        }
                    }
                }
            }
        }
        // g: 36 rows x 128 cols, coalesced
#pragma unroll
        for (int l = 0; l < 18; ++l) {
            int idx = tid + l * 256;
            int row = idx >> 7, col = idx & 127;
            int ch = row / 9, j = row - ch * 9;
            gs[row][col] = gb[(size_t)((c0 + ch) * 9 + j) * HW + col];
        }
        __syncthreads();
#pragma unroll
        for (int ch = 0; ch < 4; ++ch) {
            float gr[9];
#pragma unroll
            for (int j = 0; j < 9; ++j) gr[j] = gs[ch * 9 + j][p];
#pragma unroll
            for (int ti = 0; ti < 4; ++ti) {
                const int t = ts + ti * 2;
                float s = acc[ti];
#pragma unroll
                for (int dy = 0; dy < 3; ++dy) {
                    float x0 = xs[t][ch][hl + dy][w];
                    float x1 = xs[t][ch][hl + dy][w + 1];
                    float x2 = xs[t][ch][hl + dy][w + 2];
                    s += gr[dy * 3] * x0 + gr[dy * 3 + 1] * x1 + gr[dy * 3 + 2] * x2;
                }
                acc[ti] = s;
            }
        }
    }
#pragma unroll
    for (int ti = 0; ti < 4; ++ti) {
        const int t = ts + ti * 2;
        dpart[(((size_t)b * 8 + cs) * 8 + t) * HW + hp * 128 + p] = acc[ti];
    }
}

// ---------------- reduce partials + softmax ----------------
__global__ void __launch_bounds__(256) dots_reduce(
    const float* __restrict__ dpart, float* __restrict__ attn)
{
    const int g = blockIdx.x * 256 + threadIdx.x;   // 16384 = 4b * 4096p
    const int b = g >> 12, p = g & 4095;
    float d[8];
#pragma unroll
    for (int t = 0; t < 8; ++t) d[t] = 0.f;
#pragma unroll
    for (int cs = 0; cs < 8; ++cs)
#pragma unroll
        for (int t = 0; t < 8; ++t)
            d[t] += dpart[(((size_t)b * 8 + cs) * 8 + t) * HW + p];
    float m = d[0];
#pragma unroll
    for (int t = 1; t < 8; ++t) m = fmaxf(m, d[t]);
    float s = 0.f;
#pragma unroll
    for (int t = 0; t < 8; ++t) { d[t] = __expf(d[t] - m); s += d[t]; }
    float inv = 1.f / s;
#pragma unroll
    for (int t = 0; t < 8; ++t)
        attn[((size_t)(b * 8 + t)) * HW + p] = d[t] * inv;
}

// ---------------- fused v-GEMM, channel-split: 256 blocks ----------------
// grid (32 px-tiles, 2 cs, 4 b). Partial pooled, summed in conv6's loader.
__global__ void __launch_bounds__(256) pooled_fused(
    const float* __restrict__ x, const float* __restrict__ attn,
    const float* __restrict__ Wvt, float* __restrict__ ppart)
{
    const int bx = blockIdx.x, cs = blockIdx.y, b = blockIdx.z;
    const int r0 = bx * 2;
    const int tid = threadIdx.x, lane = tid & 31, wid = tid >> 5;
    const int tx = tid & 15, ty = tid >> 4;

    __shared__ float attn_s[8][128];
    __shared__ __align__(16) float Ws[9][128];
    __shared__ float xs[8][4][68];
    __shared__ __align__(16) float ys[9][128];

    u64 acc[8][4];
#pragma unroll
    for (int i = 0; i < 8; ++i)
#pragma unroll
        for (int j = 0; j < 4; ++j) acc[i][j] = 0ULL;

#pragma unroll
    for (int l = 0; l < 4; ++l) {
        int idx = tid + l * 256, t = idx >> 7, pp = idx & 127;
        attn_s[t][pp] = attn[((size_t)(b * 8 + t)) * HW + r0 * 64 + pp];
    }

    float prx[12], prw[5];
    auto ldx = [&](int c) {
        const float* xr = x + (((size_t)b * 8 + wid) * 256 + cs * 128 + c) * HW;
#pragma unroll
        for (int row = 0; row < 4; ++row) {
            int gh = r0 - 1 + row;
#pragma unroll
            for (int seg = 0; seg < 3; ++seg) {
                int col = lane + seg * 32;
                float v = 0.f;
                if (col < 66 && (unsigned)gh < 64u) {
                    int gw = col - 1;
                    if ((unsigned)gw < 64u) v = xr[gh * 64 + gw];
                }
                prx[row * 3 + seg] = v;
            }
        }
    };
    auto ldw = [&](int c) {
        const float* wr = Wvt + (size_t)((cs * 128 + c) * 9) * 128;
#pragma unroll
        for (int l = 0; l < 5; ++l) {
            int idx = tid + l * 256;
            if (idx < 1152) prw[l] = wr[idx];
        }
    };

    ldx(0); ldw(0);
    for (int c = 0; c < 128; ++c) {
        __syncthreads();
#pragma unroll
        for (int row = 0; row < 4; ++row)
#pragma unroll
            for (int seg = 0; seg < 3; ++seg) {
                int col = lane + seg * 32;
                if (col < 66) xs[wid][row][col] = prx[row * 3 + seg];
            }
#pragma unroll
        for (int l = 0; l < 5; ++l) {
            int idx = tid + l * 256;
            if (idx < 1152) Ws[idx >> 7][idx & 127] = prw[l];
        }
        __syncthreads();
        if (c + 1 < 128) { ldx(c + 1); ldw(c + 1); }
#pragma unroll
        for (int l = 0; l < 5; ++l) {
            int idx = tid + l * 256;
            if (idx < 1152) {
                int j = idx >> 7, pp = idx & 127;
                int dy = j / 3, dx = j - dy * 3;
                int hh = pp >> 6, w = pp & 63;
                float s = 0.f;
#pragma unroll
                for (int t = 0; t < 8; ++t)
                    s += attn_s[t][pp] * xs[t][hh + dy][w + dx];
                ys[j][pp] = s;
            }
        }
        __syncthreads();
#pragma unroll
        for (int kk = 0; kk < 9; ++kk) MICRO_STEP(Ws[kk], ys[kk], acc);
    }

#pragma unroll
    for (int i = 0; i < 8; ++i) {
        float2 u0 = unpk(acc[i][0]), u1 = unpk(acc[i][1]);
        float2 u2 = unpk(acc[i][2]), u3 = unpk(acc[i][3]);
        float* crow = ppart + ((size_t)(b * 2 + cs) * 128 + ty * 8 + i) * HW + bx * 128 + tx * 8;
        *(float4*)(crow)     = make_float4(u0.x, u0.y, u1.x, u1.y);
        *(float4*)(crow + 4) = make_float4(u2.x, u2.y, u3.x, u3.y);
    }
}

// ---------------- w_v transpose ----------------
__global__ void __launch_bounds__(256) transpose_wv(
    const float* __restrict__ wv, float* __restrict__ wvt)
{
    __shared__ float t[32][33];
    const int bx = blockIdx.x, by = blockIdx.y;
    const int lx = threadIdx.x & 31, ly = threadIdx.x >> 5;
#pragma unroll
    for (int r = 0; r < 32; r += 8)
        t[ly + r][lx] = wv[(size_t)(by * 32 + ly + r) * CK + bx * 32 + lx];
    __syncthreads();
#pragma unroll
    for (int r = 0; r < 32; r += 8)
        wvt[(size_t)(bx * 32 + ly + r) * 128 + by * 32 + lx] = t[lx][ly + r];
}

// ---------------- launch ----------------
extern "C" void kernel_launch(void* const* d_in, const int* in_sizes, int n_in,
                              void* d_out, int out_size)
{
    const float* x     = (const float*)d_in[0];
    const float* w_k   = (const float*)d_in[1];
    const float* w_q   = (const float*)d_in[2];
    const float* w_v   = (const float*)d_in[3];
    const float* w_out = (const float*)d_in[4];
    const float* b_out = (const float*)d_in[5];
    float* out = (float*)d_out;

    float *pk, *pg, *pdp, *pa, *pp, *pwvt;
    cudaGetSymbolAddress((void**)&pk, g_k);
    cudaGetSymbolAddress((void**)&pg, g_gT);
    cudaGetSymbolAddress((void**)&pdp, g_dpart);
    cudaGetSymbolAddress((void**)&pa, g_attn);
    cudaGetSymbolAddress((void**)&pp, g_ppart);
    cudaGetSymbolAddress((void**)&pwvt, g_wvt);

    // 0) transpose w_v -> [ck][d]
    transpose_wv<<<dim3(72, 4), 256>>>(w_v, pwvt);

    // 1) k partials: channel-split conv, 256 blocks
    conv3x3_f2<false, false, 2><<<dim3(32, 1, 8), 256>>>(
        w_k, x, pk, 128, 128, (long)8 * 256 * HW, (long)128 * HW, nullptr);

    // 2) gT = w_q^T * (k0 + k1)
    sgemm_f2<<<dim3(32, CK / 128, 4), 256>>>(w_q, pk, pg, 128,
                                             (long)CK, (long)2 * 128 * HW, (long)CK * HW);

    // 3a) partial dots (2-row tiles x 8 channel-splits, 1024 blocks)
    dots_split2<<<dim3(32, 8, 4), 256>>>(x, pg, pdp);
    // 3b) reduce + softmax
    dots_reduce<<<64, 256>>>(pdp, pa);

    // 4+5) fused v-GEMM, channel-split, 256 blocks -> pooled partials
    pooled_fused<<<dim3(32, 2, 4), 256>>>(x, pa, pwvt, pp);

    // 6+7) out conv (sums pooled partials in loader) + bias + T-broadcast
    conv3x3_f2<true, true, 1><<<dim3(32, 2, 4), 256>>>(
        w_out, pp, out, 256, 128, (long)2 * 128 * HW, 0L, b_out);
}

// round 5
// speedup vs baseline: 1.3299x; 1.0016x over previous
#include <cuda_runtime.h>
#include <cstdint>

// Shapes (fixed): B=4, T=8, C=256, H=W=64 (HW=4096), DH=128, CK=C*9=2304
#define HW 4096
#define CK 2304
typedef unsigned long long u64;

// ---------------- scratch (device globals; allocation-free) ----------------
__device__ float g_k[8 * 128 * HW];          // k partials [b*2+cs][128][HW]
__device__ float g_gT[4 * CK * HW];          // g transposed: [b][ck][p]
__device__ float g_dpart[4 * 8 * 8 * HW];    // partial dots [b][cs][t][p]
__device__ float g_attn[4 * 8 * HW];         // softmax weights [b][t][p]
__device__ float g_ppart[8 * 128 * HW];      // pooled partials [b*2+cs][128][HW]
__device__ float g_wvt[CK * 128];            // w_v transposed [ck][d]

// ---------------- packed f32x2 helpers ----------------
__device__ __forceinline__ u64 pack2(float v) {
    u64 r; asm("mov.b64 %0,{%1,%1};" : "=l"(r) : "f"(v)); return r;
}
__device__ __forceinline__ void ffma2(u64& d, u64 a, u64 b) {
    asm("fma.rn.f32x2 %0,%1,%2,%0;" : "+l"(d) : "l"(a), "l"(b));
}
__device__ __forceinline__ float2 unpk(u64 v) {
    float2 f; asm("mov.b64 {%0,%1},%2;" : "=f"(f.x), "=f"(f.y) : "l"(v)); return f;
}

#define MICRO_STEP(ASROW, BSROW, ACC) do {                                   \
    float4 _a0 = *(const float4*)&(ASROW)[ty * 8];                           \
    float4 _a1 = *(const float4*)&(ASROW)[ty * 8 + 4];                       \
    const u64* _bp = (const u64*)&(BSROW)[tx * 8];                           \
    u64 _b0 = _bp[0], _b1 = _bp[1], _b2 = _bp[2], _b3 = _bp[3];              \
    float _av[8] = {_a0.x, _a0.y, _a0.z, _a0.w, _a1.x, _a1.y, _a1.z, _a1.w}; \
    _Pragma("unroll")                                                        \
    for (int _i = 0; _i < 8; ++_i) {                                         \
        u64 _ai = pack2(_av[_i]);                                            \
        ffma2((ACC)[_i][0], _ai, _b0); ffma2((ACC)[_i][1], _ai, _b1);        \
        ffma2((ACC)[_i][2], _ai, _b2); ffma2((ACC)[_i][3], _ai, _b3);        \
    }                                                                        \
} while (0)

// ---------------- 3x3 conv as implicit GEMM, FFMA2 + double buffer ----------------
// CS=2: channel-split halves (blockIdx.z = b*2+cs), partial outputs.
// SUM2: X element = Xb[i] + Xb2[i] (sum of two partial buffers).
// BCAST: write all 8 frames of d_out.
template <bool BCAST, bool SUM2, int CS>
__global__ void __launch_bounds__(256) conv3x3_f2(
    const float* __restrict__ W, const float* __restrict__ X, float* __restrict__ Cout,
    int M, int CinPer, long bsX, long bsC, const float* __restrict__ bias)
{
    __shared__ __align__(16) float As[2][8][132];
    __shared__ __align__(16) float Bs[2][8][128];

    const int K = CinPer * 9;
    const int Ktot = CS * K;
    const int z = blockIdx.z;
    const int b = (CS == 2) ? (z >> 1) : z;
    const int cs = (CS == 2) ? (z & 1) : 0;
    const float* Xb = X + (size_t)b * bsX + (size_t)cs * CinPer * HW;
    const float* Xb2 = Xb + (size_t)CinPer * HW;   // used if SUM2
    const float* Wb = W + (size_t)cs * K;

    const int bm = blockIdx.y * 128, bn = blockIdx.x * 128;
    const int tid = threadIdx.x, tx = tid & 15, ty = tid >> 4;
    const int am = tid >> 3, ak = tid & 7;
    const int bk = tid >> 7, nn = tid & 127;
    const int p = bn + nn, hh = p >> 6, ww = p & 63;

    u64 acc[8][4];
#pragma unroll
    for (int i = 0; i < 8; ++i)
#pragma unroll
        for (int j = 0; j < 4; ++j) acc[i][j] = 0ULL;

    float pa[4], pb[4];
    auto ldA = [&](int k0) {
#pragma unroll
        for (int r = 0; r < 4; ++r)
            pa[r] = Wb[(size_t)(bm + am + 32 * r) * Ktot + k0 + ak];
    };
    auto ldB = [&](int k0) {
#pragma unroll
        for (int r = 0; r < 4; ++r) {
            int kb = k0 + bk + 2 * r;
            int c = kb / 9, j = kb - c * 9;
            int dy = j / 3, dx = j - dy * 3;
            int hi = hh + dy - 1, wi = ww + dx - 1;
            float v = 0.f;
            if ((unsigned)hi < 64u && (unsigned)wi < 64u) {
                size_t off = (size_t)c * HW + hi * 64 + wi;
                v = Xb[off];
                if (SUM2) v += Xb2[off];
            }
            pb[r] = v;
        }
    };
    auto sts = [&](int buf) {
#pragma unroll
        for (int r = 0; r < 4; ++r) {
            As[buf][ak][am + 32 * r] = pa[r];
            Bs[buf][bk + 2 * r][nn] = pb[r];
        }
    };

    const int nIter = K >> 3;
    ldA(0); ldB(0);
    sts(0);
    __syncthreads();
    for (int it = 0; it < nIter; ++it) {
        const int cur = it & 1;
        if (it + 1 < nIter) { ldA((it + 1) * 8); ldB((it + 1) * 8); }
#pragma unroll
        for (int kk = 0; kk < 8; ++kk) MICRO_STEP(As[cur][kk], Bs[cur][kk], acc);
        if (it + 1 < nIter) sts(cur ^ 1);
        __syncthreads();
    }

#pragma unroll
    for (int i = 0; i < 8; ++i) {
        int m = bm + ty * 8 + i;
        float bvv = bias ? bias[m] : 0.f;
        float2 u0 = unpk(acc[i][0]), u1 = unpk(acc[i][1]);
        float2 u2 = unpk(acc[i][2]), u3 = unpk(acc[i][3]);
        float4 o0 = make_float4(u0.x + bvv, u0.y + bvv, u1.x + bvv, u1.y + bvv);
        float4 o1 = make_float4(u2.x + bvv, u2.y + bvv, u3.x + bvv, u3.y + bvv);
        if (BCAST) {
#pragma unroll
            for (int t = 0; t < 8; ++t) {
                float* crow = Cout + (((size_t)(b * 8 + t)) * 256 + m) * HW + bn + tx * 8;
                *(float4*)(crow)     = o0;
                *(float4*)(crow + 4) = o1;
            }
        } else {
            float* crow = Cout + (size_t)z * bsC + (size_t)m * HW + bn + tx * 8;
            *(float4*)(crow)     = o0;
            *(float4*)(crow + 4) = o1;
        }
    }
}

// ---------------- step2 GEMM: gT[ck][p] = sum_d w_q[d][ck] * (k0+k1)[d][p] ----------------
__global__ void __launch_bounds__(256) sgemm_f2(
    const float* __restrict__ A, const float* __restrict__ B, float* __restrict__ C,
    int K, long sAk, long batchB, long batchC)
{
    __shared__ __align__(16) float As[2][8][128];
    __shared__ __align__(16) float Bs[2][8][128];

    const float* Bb = B + (size_t)blockIdx.z * batchB;
    const float* Bb2 = Bb + (size_t)128 * HW;
    float*       Cb = C + (size_t)blockIdx.z * batchC;
    const int bm = blockIdx.y * 128, bn = blockIdx.x * 128;
    const int tid = threadIdx.x, tx = tid & 15, ty = tid >> 4;
    const int kk0 = tid >> 7, nn = tid & 127;

    u64 acc[8][4];
#pragma unroll
    for (int i = 0; i < 8; ++i)
#pragma unroll
        for (int j = 0; j < 4; ++j) acc[i][j] = 0ULL;

    float pa[4], pb[4];
    auto ld = [&](int k0) {
#pragma unroll
        for (int r = 0; r < 4; ++r) {
            size_t boff = (size_t)(k0 + kk0 + 2 * r) * HW + bn + nn;
            pa[r] = A[(size_t)(bm + nn) + (size_t)(k0 + kk0 + 2 * r) * sAk];
            pb[r] = Bb[boff] + Bb2[boff];
        }
    };
    auto sts = [&](int buf) {
#pragma unroll
        for (int r = 0; r < 4; ++r) {
            As[buf][kk0 + 2 * r][nn] = pa[r];
            Bs[buf][kk0 + 2 * r][nn] = pb[r];
        }
    };

    const int nIter = K >> 3;
    ld(0);
    sts(0);
    __syncthreads();
    for (int it = 0; it < nIter; ++it) {
        const int cur = it & 1;
        if (it + 1 < nIter) ld((it + 1) * 8);
#pragma unroll
        for (int kk = 0; kk < 8; ++kk) MICRO_STEP(As[cur][kk], Bs[cur][kk], acc);
        if (it + 1 < nIter) sts(cur ^ 1);
        __syncthreads();
    }

#pragma unroll
    for (int i = 0; i < 8; ++i) {
        float2 u0 = unpk(acc[i][0]), u1 = unpk(acc[i][1]);
        float2 u2 = unpk(acc[i][2]), u3 = unpk(acc[i][3]);
        float* crow = Cb + (size_t)(bm + ty * 8 + i) * HW + bn + tx * 8;
        *(float4*)(crow)     = make_float4(u0.x, u0.y, u1.x, u1.y);
        *(float4*)(crow + 4) = make_float4(u2.x, u2.y, u3.x, u3.y);
    }
}

// ---------------- dots, 2-row tiles + channel split: 1024 blocks ----------------
// grid (hp=32, cs=8, b=4), 256 thr. Block: rows 2hp..2hp+1 (128 px), 32 channels.
__global__ void __launch_bounds__(256) dots_split2(
    const float* __restrict__ x, const float* __restrict__ gT, float* __restrict__ dpart)
{
    const int hp = blockIdx.x, cs = blockIdx.y, b = blockIdx.z;
    const int tid = threadIdx.x, lane = tid & 31, wid = tid >> 5;
    const int p = tid & 127, ts = tid >> 7;          // ts in {0,1}; t = ts + 2*ti
    const int hl = p >> 6, w = p & 63;

    __shared__ float xs[8][4][4][68];   // [t][ch][row][col]
    __shared__ float gs[36][128];       // [ch*9+j][p]

    const float* xb = x + (size_t)b * 8 * 256 * HW;
    const float* gb = gT + (size_t)b * CK * HW + hp * 128;

    float acc[4] = {0.f, 0.f, 0.f, 0.f};
    for (int cg = 0; cg < 8; ++cg) {
        const int c0 = cs * 32 + cg * 4;
        __syncthreads();
        // x: warp wid -> t = wid; 4 channels x 4 rows (2hp-1..2hp+2) x 66 cols
        {
            const float* xt = xb + (size_t)wid * 256 * HW;
#pragma unroll
            for (int ch = 0; ch < 4; ++ch) {
                const float* xr = xt + (size_t)(c0 + ch) * HW;
#pragma unroll
                for (int row = 0; row < 4; ++row) {
                    int gh = 2 * hp - 1 + row;
#pragma unroll
                    for (int seg = 0; seg < 3; ++seg) {
                        int col = lane + seg * 32;
                        if (col < 66) {
                            int gw = col - 1;
                            float v = 0.f;
                            if ((unsigned)gh < 64u && (unsigned)gw < 64u)
                                v = xr[gh * 64 + gw];
                            xs[wid][ch][row][col] = v;
                        }
                    }
                }
            }
        }
        // g: 36 rows x 128 cols, coalesced
#pragma unroll
        for (int l = 0; l < 18; ++l) {
            int idx = tid + l * 256;
            int row = idx >> 7, col = idx & 127;
            int ch = row / 9, j = row - ch * 9;
            gs[row][col] = gb[(size_t)((c0 + ch) * 9 + j) * HW + col];
        }
        __syncthreads();
#pragma unroll
        for (int ch = 0; ch < 4; ++ch) {
            float gr[9];
#pragma unroll
            for (int j = 0; j < 9; ++j) gr[j] = gs[ch * 9 + j][p];
#pragma unroll
            for (int ti = 0; ti < 4; ++ti) {
                const int t = ts + ti * 2;
                float s = acc[ti];
#pragma unroll
                for (int dy = 0; dy < 3; ++dy) {
                    float x0 = xs[t][ch][hl + dy][w];
                    float x1 = xs[t][ch][hl + dy][w + 1];
                    float x2 = xs[t][ch][hl + dy][w + 2];
                    s += gr[dy * 3] * x0 + gr[dy * 3 + 1] * x1 + gr[dy * 3 + 2] * x2;
                }
                acc[ti] = s;
            }
        }
    }
#pragma unroll
    for (int ti = 0; ti < 4; ++ti) {
        const int t = ts + ti * 2;
        dpart[(((size_t)b * 8 + cs) * 8 + t) * HW + hp * 128 + p] = acc[ti];
    }
}

// ---------------- reduce partials + softmax ----------------
__global__ void __launch_bounds__(256) dots_reduce(
    const float* __restrict__ dpart, float* __restrict__ attn)
{
    const int g = blockIdx.x * 256 + threadIdx.x;   // 16384 = 4b * 4096p
    const int b = g >> 12, p = g & 4095;
    float d[8];
#pragma unroll
    for (int t = 0; t < 8; ++t) d[t] = 0.f;
#pragma unroll
    for (int cs = 0; cs < 8; ++cs)
#pragma unroll
        for (int t = 0; t < 8; ++t)
            d[t] += dpart[(((size_t)b * 8 + cs) * 8 + t) * HW + p];
    float m = d[0];
#pragma unroll
    for (int t = 1; t < 8; ++t) m = fmaxf(m, d[t]);
    float s = 0.f;
#pragma unroll
    for (int t = 0; t < 8; ++t) { d[t] = __expf(d[t] - m); s += d[t]; }
    float inv = 1.f / s;
#pragma unroll
    for (int t = 0; t < 8; ++t)
        attn[((size_t)(b * 8 + t)) * HW + p] = d[t] * inv;
}

// ---------------- fused v-GEMM, channel-split: 256 blocks ----------------
// grid (32 px-tiles, 2 cs, 4 b). Partial pooled, summed in conv6's loader.
__global__ void __launch_bounds__(256) pooled_fused(
    const float* __restrict__ x, const float* __restrict__ attn,
    const float* __restrict__ Wvt, float* __restrict__ ppart)
{
    const int bx = blockIdx.x, cs = blockIdx.y, b = blockIdx.z;
    const int r0 = bx * 2;
    const int tid = threadIdx.x, lane = tid & 31, wid = tid >> 5;
    const int tx = tid & 15, ty = tid >> 4;

    __shared__ float attn_s[8][128];
    __shared__ __align__(16) float Ws[9][128];
    __shared__ float xs[8][4][68];
    __shared__ __align__(16) float ys[9][128];

    u64 acc[8][4];
#pragma unroll
    for (int i = 0; i < 8; ++i)
#pragma unroll
        for (int j = 0; j < 4; ++j) acc[i][j] = 0ULL;

#pragma unroll
    for (int l = 0; l < 4; ++l) {
        int idx = tid + l * 256, t = idx >> 7, pp = idx & 127;
        attn_s[t][pp] = attn[((size_t)(b * 8 + t)) * HW + r0 * 64 + pp];
    }

    float prx[12], prw[5];
    auto ldx = [&](int c) {
        const float* xr = x + (((size_t)b * 8 + wid) * 256 + cs * 128 + c) * HW;
#pragma unroll
        for (int row = 0; row < 4; ++row) {
            int gh = r0 - 1 + row;
#pragma unroll
            for (int seg = 0; seg < 3; ++seg) {
                int col = lane + seg * 32;
                float v = 0.f;
                if (col < 66 && (unsigned)gh < 64u) {
                    int gw = col - 1;
                    if ((unsigned)gw < 64u) v = xr[gh * 64 + gw];
                }
                prx[row * 3 + seg] = v;
            }
        }
    };
    auto ldw = [&](int c) {
        const float* wr = Wvt + (size_t)((cs * 128 + c) * 9) * 128;
#pragma unroll
        for (int l = 0; l < 5; ++l) {
            int idx = tid + l * 256;
            if (idx < 1152) prw[l] = wr[idx];
        }
    };

    ldx(0); ldw(0);
    for (int c = 0; c < 128; ++c) {
        __syncthreads();
#pragma unroll
        for (int row = 0; row < 4; ++row)
#pragma unroll
            for (int seg = 0; seg < 3; ++seg) {
                int col = lane + seg * 32;
                if (col < 66) xs[wid][row][col] = prx[row * 3 + seg];
            }
#pragma unroll
        for (int l = 0; l < 5; ++l) {
            int idx = tid + l * 256;
            if (idx < 1152) Ws[idx >> 7][idx & 127] = prw[l];
        }
        __syncthreads();
        if (c + 1 < 128) { ldx(c + 1); ldw(c + 1); }
#pragma unroll
        for (int l = 0; l < 5; ++l) {
            int idx = tid + l * 256;
            if (idx < 1152) {
                int j = idx >> 7, pp = idx & 127;
                int dy = j / 3, dx = j - dy * 3;
                int hh = pp >> 6, w = pp & 63;
                float s = 0.f;
#pragma unroll
                for (int t = 0; t < 8; ++t)
                    s += attn_s[t][pp] * xs[t][hh + dy][w + dx];
                ys[j][pp] = s;
            }
        }
        __syncthreads();
#pragma unroll
        for (int kk = 0; kk < 9; ++kk) MICRO_STEP(Ws[kk], ys[kk], acc);
    }

#pragma unroll
    for (int i = 0; i < 8; ++i) {
        float2 u0 = unpk(acc[i][0]), u1 = unpk(acc[i][1]);
        float2 u2 = unpk(acc[i][2]), u3 = unpk(acc[i][3]);
        float* crow = ppart + ((size_t)(b * 2 + cs) * 128 + ty * 8 + i) * HW + bx * 128 + tx * 8;
        *(float4*)(crow)     = make_float4(u0.x, u0.y, u1.x, u1.y);
        *(float4*)(crow + 4) = make_float4(u2.x, u2.y, u3.x, u3.y);
    }
}

// ---------------- w_v transpose ----------------
__global__ void __launch_bounds__(256) transpose_wv(
    const float* __restrict__ wv, float* __restrict__ wvt)
{
    __shared__ float t[32][33];
    const int bx = blockIdx.x, by = blockIdx.y;
    const int lx = threadIdx.x & 31, ly = threadIdx.x >> 5;
#pragma unroll
    for (int r = 0; r < 32; r += 8)
        t[ly + r][lx] = wv[(size_t)(by * 32 + ly + r) * CK + bx * 32 + lx];
    __syncthreads();
#pragma unroll
    for (int r = 0; r < 32; r += 8)
        wvt[(size_t)(bx * 32 + ly + r) * 128 + by * 32 + lx] = t[lx][ly + r];
}

// ---------------- launch ----------------
extern "C" void kernel_launch(void* const* d_in, const int* in_sizes, int n_in,
                              void* d_out, int out_size)
{
    const float* x     = (const float*)d_in[0];
    const float* w_k   = (const float*)d_in[1];
    const float* w_q   = (const float*)d_in[2];
    const float* w_v   = (const float*)d_in[3];
    const float* w_out = (const float*)d_in[4];
    const float* b_out = (const float*)d_in[5];
    float* out = (float*)d_out;

    float *pk, *pg, *pdp, *pa, *pp, *pwvt;
    cudaGetSymbolAddress((void**)&pk, g_k);
    cudaGetSymbolAddress((void**)&pg, g_gT);
    cudaGetSymbolAddress((void**)&pdp, g_dpart);
    cudaGetSymbolAddress((void**)&pa, g_attn);
    cudaGetSymbolAddress((void**)&pp, g_ppart);
    cudaGetSymbolAddress((void**)&pwvt, g_wvt);

    // 0) transpose w_v -> [ck][d]
    transpose_wv<<<dim3(72, 4), 256>>>(w_v, pwvt);

    // 1) k partials: channel-split conv, 256 blocks
    conv3x3_f2<false, false, 2><<<dim3(32, 1, 8), 256>>>(
        w_k, x, pk, 128, 128, (long)8 * 256 * HW, (long)128 * HW, nullptr);

    // 2) gT = w_q^T * (k0 + k1)
    sgemm_f2<<<dim3(32, CK / 128, 4), 256>>>(w_q, pk, pg, 128,
                                             (long)CK, (long)2 * 128 * HW, (long)CK * HW);

    // 3a) partial dots (2-row tiles x 8 channel-splits, 1024 blocks)
    dots_split2<<<dim3(32, 8, 4), 256>>>(x, pg, pdp);
    // 3b) reduce + softmax
    dots_reduce<<<64, 256>>>(pdp, pa);

    // 4+5) fused v-GEMM, channel-split, 256 blocks -> pooled partials
    pooled_fused<<<dim3(32, 2, 4), 256>>>(x, pa, pwvt, pp);

    // 6+7) out conv (sums pooled partials in loader) + bias + T-broadcast
    conv3x3_f2<true, true, 1><<<dim3(32, 2, 4), 256>>>(
        w_out, pp, out, 256, 128, (long)2 * 128 * HW, 0L, b_out);
}